// round 1
// baseline (speedup 1.0000x reference)
#include <cuda_runtime.h>
#include <cuda_bf16.h>

// Blur (upfirdn2d, 4x4 FIR kernel = outer([1,3,3,1])/16, pad=(2,1), stride 1)
// x: (B,C,256,256) fp32 -> y: same shape.
// y[p][q] = sum_{a,b} K[a][b] * x[p+1-a][q+1-b]  (zero padded)
//
// Fast path (kernel == outer([1,3,3,1])/16, verified at runtime):
//   separable, immediate-coefficient FMAs, vertical streaming with a
//   4-row rotating h-window in registers. Each thread: 8 cols x 32 rows.
// Slow path (any other kernel): direct 16-tap, exact, rarely taken.

#define HH 256
#define WW 256

// Compute one horizontal-filtered row segment (8 values), pre-scaled by 1/16.
// h[i] = (x[q+1] + 3x[q] + 3x[q-1] + x[q-2]) * 0.0625  for q = q0+i
__device__ __forceinline__ void hrow_fast(const float* __restrict__ xin,
                                          int r, int q0, float* __restrict__ h) {
    if (r < 0 || r >= HH) {
        #pragma unroll
        for (int i = 0; i < 8; i++) h[i] = 0.0f;
        return;
    }
    const float* rowp = xin + r * WW;
    float v[11];
    if (q0 > 0) {
        float2 l = *reinterpret_cast<const float2*>(rowp + q0 - 2);
        v[0] = l.x; v[1] = l.y;
    } else {
        v[0] = 0.0f; v[1] = 0.0f;
    }
    float4 a = *reinterpret_cast<const float4*>(rowp + q0);
    float4 b = *reinterpret_cast<const float4*>(rowp + q0 + 4);
    v[2] = a.x; v[3] = a.y; v[4] = a.z; v[5] = a.w;
    v[6] = b.x; v[7] = b.y; v[8] = b.z; v[9] = b.w;
    v[10] = (q0 + 8 < WW) ? rowp[q0 + 8] : 0.0f;

    #pragma unroll
    for (int i = 0; i < 8; i++) {
        float t = fmaf(v[i + 2], 3.0f, v[i + 3]);   // 3*x[q] + x[q+1]
        t = fmaf(v[i + 1], 3.0f, t);                // + 3*x[q-1]
        t = t + v[i];                               // + x[q-2]
        h[i] = t * 0.0625f;                         // * 1/16
    }
}

// y = hD + 3*hC + 3*hB + hA   (hD newest = h(p+1), hA oldest = h(p-2))
__device__ __forceinline__ void emit_row(const float* __restrict__ hA,
                                         const float* __restrict__ hB,
                                         const float* __restrict__ hC,
                                         const float* __restrict__ hD,
                                         float* __restrict__ outp) {
    float y[8];
    #pragma unroll
    for (int i = 0; i < 8; i++) {
        float u = fmaf(hC[i], 3.0f, hD[i]);
        u = fmaf(hB[i], 3.0f, u);
        y[i] = u + hA[i];
    }
    float4 s0 = make_float4(y[0], y[1], y[2], y[3]);
    float4 s1 = make_float4(y[4], y[5], y[6], y[7]);
    *reinterpret_cast<float4*>(outp)     = s0;
    *reinterpret_cast<float4*>(outp + 4) = s1;
}

__global__ __launch_bounds__(256, 3)
void Blur_455266533538_kernel(const float* __restrict__ x,
                              const float* __restrict__ kern,
                              float* __restrict__ out, int nimg) {
    int img = blockIdx.x;
    if (img >= nimg) return;

    int tid   = threadIdx.x;
    int seg   = tid & 31;    // lane = horizontal segment -> coalesced-ish rows
    int chunk = tid >> 5;    // warp = row chunk (uniform row bounds per warp)
    int q0 = seg * 8;
    int r0 = chunk * 32;

    const float* xin = x   + (size_t)img * (HH * WW);
    float*       yo  = out + (size_t)img * (HH * WW);

    // Verify the kernel matches outer([1,3,3,1])/16 (exact in fp32).
    bool fast = true;
    const float wv0 = 1.0f, wv1 = 3.0f;
    float wva[4] = {wv0, wv1, wv1, wv0};
    #pragma unroll
    for (int a = 0; a < 4; a++) {
        #pragma unroll
        for (int b = 0; b < 4; b++) {
            float expect = wva[a] * wva[b] * 0.0625f;
            if (fabsf(__ldg(&kern[a * 4 + b]) - expect) > 1e-7f) fast = false;
        }
    }

    if (fast) {
        float h0[8], h1[8], h2[8], h3[8];
        hrow_fast(xin, r0 - 2, q0, h0);
        hrow_fast(xin, r0 - 1, q0, h1);
        hrow_fast(xin, r0,     q0, h2);

        #pragma unroll 1
        for (int pp = 0; pp < 32; pp += 4) {
            int p = r0 + pp;
            hrow_fast(xin, p + 1, q0, h3);
            emit_row(h0, h1, h2, h3, yo + (p + 0) * WW + q0);
            hrow_fast(xin, p + 2, q0, h0);
            emit_row(h1, h2, h3, h0, yo + (p + 1) * WW + q0);
            hrow_fast(xin, p + 3, q0, h1);
            emit_row(h2, h3, h0, h1, yo + (p + 2) * WW + q0);
            hrow_fast(xin, p + 4, q0, h2);
            emit_row(h3, h0, h1, h2, yo + (p + 3) * WW + q0);
        }
    } else {
        // Exact general fallback: direct 16-tap convolution.
        float kk[16];
        #pragma unroll
        for (int i = 0; i < 16; i++) kk[i] = __ldg(&kern[i]);

        for (int pr = 0; pr < 32; pr++) {
            int p = r0 + pr;
            for (int qc = 0; qc < 8; qc++) {
                int q = q0 + qc;
                float acc = 0.0f;
                #pragma unroll
                for (int a = 0; a < 4; a++) {
                    int rr = p + 1 - a;
                    if (rr < 0 || rr >= HH) continue;
                    #pragma unroll
                    for (int b = 0; b < 4; b++) {
                        int cc = q + 1 - b;
                        if (cc < 0 || cc >= WW) continue;
                        acc = fmaf(kk[a * 4 + b], xin[rr * WW + cc], acc);
                    }
                }
                yo[p * WW + q] = acc;
            }
        }
    }
}

extern "C" void kernel_launch(void* const* d_in, const int* in_sizes, int n_in,
                              void* d_out, int out_size) {
    const float* x    = (const float*)d_in[0];
    const float* kern = (const float*)d_in[1];
    float* out = (float*)d_out;

    int n = in_sizes[0];
    int nimg = n / (HH * WW);   // B*C images of 256x256

    Blur_455266533538_kernel<<<nimg, 256>>>(x, kern, out, nimg);
}

// round 2
// speedup vs baseline: 1.0960x; 1.0960x over previous
#include <cuda_runtime.h>
#include <cuda_bf16.h>

// Blur (upfirdn2d, 4x4 FIR kernel = outer([1,3,3,1])/16, pad=(2,1), stride 1)
// x: (B,C,256,256) fp32 -> y: same shape.
// y[p][q] = sum_{a,b} K[a][b] * x[p+1-a][q+1-b]  (zero padded)
//
// R2: same separable immediate-FMA math as R1, but 4x more CTAs
// (64-row tiles, 8 rows/thread) to fix the 2.3-wave tail that left
// DRAM 35% idle. Fallback path (arbitrary kernel) kept, exact.

#define HH 256
#define WW 256
#define TILE_ROWS 64          // rows per CTA
#define ROWS_PER_THREAD 8     // rows per thread (8 warps of row-chunks)

// One horizontal-filtered row segment (8 values), pre-scaled by 1/16.
// h[i] = (x[q+1] + 3x[q] + 3x[q-1] + x[q-2]) * 0.0625  for q = q0+i
__device__ __forceinline__ void hrow_fast(const float* __restrict__ xin,
                                          int r, int q0, float* __restrict__ h) {
    if (r < 0 || r >= HH) {
        #pragma unroll
        for (int i = 0; i < 8; i++) h[i] = 0.0f;
        return;
    }
    const float* rowp = xin + r * WW;
    float v[11];
    if (q0 > 0) {
        float2 l = *reinterpret_cast<const float2*>(rowp + q0 - 2);
        v[0] = l.x; v[1] = l.y;
    } else {
        v[0] = 0.0f; v[1] = 0.0f;
    }
    float4 a = *reinterpret_cast<const float4*>(rowp + q0);
    float4 b = *reinterpret_cast<const float4*>(rowp + q0 + 4);
    v[2] = a.x; v[3] = a.y; v[4] = a.z; v[5] = a.w;
    v[6] = b.x; v[7] = b.y; v[8] = b.z; v[9] = b.w;
    v[10] = (q0 + 8 < WW) ? rowp[q0 + 8] : 0.0f;

    #pragma unroll
    for (int i = 0; i < 8; i++) {
        float t = fmaf(v[i + 2], 3.0f, v[i + 3]);   // 3*x[q] + x[q+1]
        t = fmaf(v[i + 1], 3.0f, t);                // + 3*x[q-1]
        t = t + v[i];                               // + x[q-2]
        h[i] = t * 0.0625f;                         // * 1/16
    }
}

// y = hD + 3*hC + 3*hB + hA   (hD newest = h(p+1), hA oldest = h(p-2))
__device__ __forceinline__ void emit_row(const float* __restrict__ hA,
                                         const float* __restrict__ hB,
                                         const float* __restrict__ hC,
                                         const float* __restrict__ hD,
                                         float* __restrict__ outp) {
    float y[8];
    #pragma unroll
    for (int i = 0; i < 8; i++) {
        float u = fmaf(hC[i], 3.0f, hD[i]);
        u = fmaf(hB[i], 3.0f, u);
        y[i] = u + hA[i];
    }
    *reinterpret_cast<float4*>(outp)     = make_float4(y[0], y[1], y[2], y[3]);
    *reinterpret_cast<float4*>(outp + 4) = make_float4(y[4], y[5], y[6], y[7]);
}

__global__ __launch_bounds__(256, 3)
void Blur_455266533538_kernel(const float* __restrict__ x,
                              const float* __restrict__ kern,
                              float* __restrict__ out, int nimg) {
    int tile = blockIdx.x & 3;            // 4 tiles of 64 rows per image
    int img  = blockIdx.x >> 2;
    if (img >= nimg) return;

    int tid   = threadIdx.x;
    int seg   = tid & 31;                 // lane -> horizontal segment
    int chunk = tid >> 5;                 // warp -> 8-row chunk
    int q0 = seg * 8;
    int r0 = tile * TILE_ROWS + chunk * ROWS_PER_THREAD;

    const float* xin = x   + (size_t)img * (HH * WW);
    float*       yo  = out + (size_t)img * (HH * WW);

    // Verify the kernel matches outer([1,3,3,1])/16 (exact in fp32).
    bool fast = true;
    float wva[4] = {1.0f, 3.0f, 3.0f, 1.0f};
    #pragma unroll
    for (int a = 0; a < 4; a++) {
        #pragma unroll
        for (int b = 0; b < 4; b++) {
            float expect = wva[a] * wva[b] * 0.0625f;
            if (fabsf(__ldg(&kern[a * 4 + b]) - expect) > 1e-7f) fast = false;
        }
    }

    if (fast) {
        float h0[8], h1[8], h2[8], h3[8];
        hrow_fast(xin, r0 - 2, q0, h0);
        hrow_fast(xin, r0 - 1, q0, h1);
        hrow_fast(xin, r0,     q0, h2);

        #pragma unroll
        for (int pp = 0; pp < ROWS_PER_THREAD; pp += 4) {
            int p = r0 + pp;
            hrow_fast(xin, p + 1, q0, h3);
            emit_row(h0, h1, h2, h3, yo + (p + 0) * WW + q0);
            hrow_fast(xin, p + 2, q0, h0);
            emit_row(h1, h2, h3, h0, yo + (p + 1) * WW + q0);
            hrow_fast(xin, p + 3, q0, h1);
            emit_row(h2, h3, h0, h1, yo + (p + 2) * WW + q0);
            hrow_fast(xin, p + 4, q0, h2);
            emit_row(h3, h0, h1, h2, yo + (p + 3) * WW + q0);
        }
    } else {
        // Exact general fallback: direct 16-tap convolution.
        float kk[16];
        #pragma unroll
        for (int i = 0; i < 16; i++) kk[i] = __ldg(&kern[i]);

        for (int pr = 0; pr < ROWS_PER_THREAD; pr++) {
            int p = r0 + pr;
            for (int qc = 0; qc < 8; qc++) {
                int q = q0 + qc;
                float acc = 0.0f;
                #pragma unroll
                for (int a = 0; a < 4; a++) {
                    int rr = p + 1 - a;
                    if (rr < 0 || rr >= HH) continue;
                    #pragma unroll
                    for (int b = 0; b < 4; b++) {
                        int cc = q + 1 - b;
                        if (cc < 0 || cc >= WW) continue;
                        acc = fmaf(kk[a * 4 + b], xin[rr * WW + cc], acc);
                    }
                }
                yo[p * WW + q] = acc;
            }
        }
    }
}

extern "C" void kernel_launch(void* const* d_in, const int* in_sizes, int n_in,
                              void* d_out, int out_size) {
    const float* x    = (const float*)d_in[0];
    const float* kern = (const float*)d_in[1];
    float* out = (float*)d_out;

    int n = in_sizes[0];
    int nimg = n / (HH * WW);   // B*C images of 256x256

    Blur_455266533538_kernel<<<nimg * 4, 256>>>(x, kern, out, nimg);
}

// round 3
// speedup vs baseline: 1.1108x; 1.0135x over previous
#include <cuda_runtime.h>
#include <cuda_bf16.h>

// Blur (upfirdn2d, 4x4 FIR kernel = outer([1,3,3,1])/16, pad=(2,1), stride 1)
// x: (B,C,256,256) fp32 -> y: same shape.
// y[p][q] = sum_{a,b} K[a][b] * x[p+1-a][q+1-b]  (zero padded)
//
// R3: shuffle-based horizontal halo — each lane loads ONLY its two aligned
// float4s; left-2/right-1 halo comes from neighbor lanes via warp shuffle
// (a warp spans the full 256-col row, so lane 0/31 boundaries are exactly
// the zero-padding). Kills the 32B-strided float2/scalar loads that were
// saturating L1tex (63%) and starving DRAM. 4 CTAs/SM via launch bounds.

#define HH 256
#define WW 256
#define TILE_ROWS 64          // rows per CTA
#define ROWS_PER_THREAD 8     // rows per thread (8 warps of row-chunks)

// One horizontal-filtered row segment (8 values), pre-scaled by 1/16.
// h[i] = (x[q+1] + 3x[q] + 3x[q-1] + x[q-2]) * 0.0625  for q = q0+i
// Loads: two aligned float4 per lane; halo via warp shuffle.
// NOTE: must be called with warp-uniform r (shuffles are warp-collective).
__device__ __forceinline__ void hrow_fast(const float* __restrict__ xin,
                                          int r, int q0, int lane,
                                          float* __restrict__ h) {
    if (r < 0 || r >= HH) {
        #pragma unroll
        for (int i = 0; i < 8; i++) h[i] = 0.0f;
        return;
    }
    const float* rowp = xin + r * WW;
    float4 a = *reinterpret_cast<const float4*>(rowp + q0);
    float4 b = *reinterpret_cast<const float4*>(rowp + q0 + 4);

    // halo: lane i needs x[8i-2], x[8i-1] (lane i-1's b.z, b.w)
    //       and x[8i+8] (lane i+1's a.x). Row edges are zero padding.
    float lm2 = __shfl_up_sync(0xFFFFFFFFu, b.z, 1);
    float lm1 = __shfl_up_sync(0xFFFFFFFFu, b.w, 1);
    float rp1 = __shfl_down_sync(0xFFFFFFFFu, a.x, 1);
    if (lane == 0)  { lm2 = 0.0f; lm1 = 0.0f; }
    if (lane == 31) { rp1 = 0.0f; }

    float v[11];
    v[0] = lm2; v[1] = lm1;
    v[2] = a.x; v[3] = a.y; v[4] = a.z; v[5] = a.w;
    v[6] = b.x; v[7] = b.y; v[8] = b.z; v[9] = b.w;
    v[10] = rp1;

    #pragma unroll
    for (int i = 0; i < 8; i++) {
        float t = fmaf(v[i + 2], 3.0f, v[i + 3]);   // 3*x[q] + x[q+1]
        t = fmaf(v[i + 1], 3.0f, t);                // + 3*x[q-1]
        t = t + v[i];                               // + x[q-2]
        h[i] = t * 0.0625f;                         // * 1/16
    }
}

// y = hD + 3*hC + 3*hB + hA   (hD newest = h(p+1), hA oldest = h(p-2))
__device__ __forceinline__ void emit_row(const float* __restrict__ hA,
                                         const float* __restrict__ hB,
                                         const float* __restrict__ hC,
                                         const float* __restrict__ hD,
                                         float* __restrict__ outp) {
    float y[8];
    #pragma unroll
    for (int i = 0; i < 8; i++) {
        float u = fmaf(hC[i], 3.0f, hD[i]);
        u = fmaf(hB[i], 3.0f, u);
        y[i] = u + hA[i];
    }
    *reinterpret_cast<float4*>(outp)     = make_float4(y[0], y[1], y[2], y[3]);
    *reinterpret_cast<float4*>(outp + 4) = make_float4(y[4], y[5], y[6], y[7]);
}

__global__ __launch_bounds__(256, 4)
void Blur_455266533538_kernel(const float* __restrict__ x,
                              const float* __restrict__ kern,
                              float* __restrict__ out, int nimg) {
    int tile = blockIdx.x & 3;            // 4 tiles of 64 rows per image
    int img  = blockIdx.x >> 2;
    if (img >= nimg) return;

    int tid   = threadIdx.x;
    int lane  = tid & 31;                 // lane -> horizontal segment
    int chunk = tid >> 5;                 // warp -> 8-row chunk
    int q0 = lane * 8;
    int r0 = tile * TILE_ROWS + chunk * ROWS_PER_THREAD;

    const float* xin = x   + (size_t)img * (HH * WW);
    float*       yo  = out + (size_t)img * (HH * WW);

    // Verify the kernel matches outer([1,3,3,1])/16 (exact in fp32).
    bool fast = true;
    float wva[4] = {1.0f, 3.0f, 3.0f, 1.0f};
    #pragma unroll
    for (int a = 0; a < 4; a++) {
        #pragma unroll
        for (int b = 0; b < 4; b++) {
            float expect = wva[a] * wva[b] * 0.0625f;
            if (fabsf(__ldg(&kern[a * 4 + b]) - expect) > 1e-7f) fast = false;
        }
    }

    if (fast) {
        float h0[8], h1[8], h2[8], h3[8];
        hrow_fast(xin, r0 - 2, q0, lane, h0);
        hrow_fast(xin, r0 - 1, q0, lane, h1);
        hrow_fast(xin, r0,     q0, lane, h2);

        #pragma unroll
        for (int pp = 0; pp < ROWS_PER_THREAD; pp += 4) {
            int p = r0 + pp;
            hrow_fast(xin, p + 1, q0, lane, h3);
            emit_row(h0, h1, h2, h3, yo + (p + 0) * WW + q0);
            hrow_fast(xin, p + 2, q0, lane, h0);
            emit_row(h1, h2, h3, h0, yo + (p + 1) * WW + q0);
            hrow_fast(xin, p + 3, q0, lane, h1);
            emit_row(h2, h3, h0, h1, yo + (p + 2) * WW + q0);
            hrow_fast(xin, p + 4, q0, lane, h2);
            emit_row(h3, h0, h1, h2, yo + (p + 3) * WW + q0);
        }
    } else {
        // Exact general fallback: direct 16-tap convolution.
        float kk[16];
        #pragma unroll
        for (int i = 0; i < 16; i++) kk[i] = __ldg(&kern[i]);

        for (int pr = 0; pr < ROWS_PER_THREAD; pr++) {
            int p = r0 + pr;
            for (int qc = 0; qc < 8; qc++) {
                int q = q0 + qc;
                float acc = 0.0f;
                #pragma unroll
                for (int a = 0; a < 4; a++) {
                    int rr = p + 1 - a;
                    if (rr < 0 || rr >= HH) continue;
                    #pragma unroll
                    for (int b = 0; b < 4; b++) {
                        int cc = q + 1 - b;
                        if (cc < 0 || cc >= WW) continue;
                        acc = fmaf(kk[a * 4 + b], xin[rr * WW + cc], acc);
                    }
                }
                yo[p * WW + q] = acc;
            }
        }
    }
}

extern "C" void kernel_launch(void* const* d_in, const int* in_sizes, int n_in,
                              void* d_out, int out_size) {
    const float* x    = (const float*)d_in[0];
    const float* kern = (const float*)d_in[1];
    float* out = (float*)d_out;

    int n = in_sizes[0];
    int nimg = n / (HH * WW);   // B*C images of 256x256

    Blur_455266533538_kernel<<<nimg * 4, 256>>>(x, kern, out, nimg);
}

// round 4
// speedup vs baseline: 1.2223x; 1.1004x over previous
#include <cuda_runtime.h>
#include <cuda_bf16.h>

// Blur (upfirdn2d, 4x4 FIR = outer([1,3,3,1])/16, pad=(2,1), stride 1)
// x: (B,C,256,256) fp32 -> y: same shape.
// y[p][q] = sum_{a,b} K[a][b] * x[p+1-a][q+1-b]  (zero padded)
//
// R4: front-batched loads. Each steady-state iteration issues all 8
// LDG.128 for the next 4 input rows FIRST (MLP_p1=8), then consumes them
// (shuffle halo + separable immediate-FMA FIR) in arrival order.
// Rotating 4-row h-window in registers; occ target 3 CTAs/SM (84 regs).

#define HH 256
#define WW 256
#define TILE_ROWS 64
#define ROWS_PER_THREAD 8

// Load one row segment (two aligned float4), zero-filled out of range.
// r must be warp-uniform.
__device__ __forceinline__ void ldrow(const float* __restrict__ xin,
                                      int r, int q0, float4& a, float4& b) {
    if (r >= 0 && r < HH) {
        const float4* p = reinterpret_cast<const float4*>(xin + r * WW + q0);
        a = p[0];
        b = p[1];
    } else {
        a = make_float4(0.f, 0.f, 0.f, 0.f);
        b = a;
    }
}

// Horizontal FIR on a staged row: h[i] = (x[q+1]+3x[q]+3x[q-1]+x[q-2])/16.
// Halo via warp shuffle (warp spans the full 256-col row; lane 0/31 edges
// are exactly the conv zero-padding). Warp-collective.
__device__ __forceinline__ void hmath(float4 a, float4 b, int lane,
                                      float* __restrict__ h) {
    float lm2 = __shfl_up_sync(0xFFFFFFFFu, b.z, 1);
    float lm1 = __shfl_up_sync(0xFFFFFFFFu, b.w, 1);
    float rp1 = __shfl_down_sync(0xFFFFFFFFu, a.x, 1);
    if (lane == 0)  { lm2 = 0.0f; lm1 = 0.0f; }
    if (lane == 31) { rp1 = 0.0f; }

    float v[11];
    v[0] = lm2; v[1] = lm1;
    v[2] = a.x; v[3] = a.y; v[4] = a.z; v[5] = a.w;
    v[6] = b.x; v[7] = b.y; v[8] = b.z; v[9] = b.w;
    v[10] = rp1;

    #pragma unroll
    for (int i = 0; i < 8; i++) {
        float t = fmaf(v[i + 2], 3.0f, v[i + 3]);
        t = fmaf(v[i + 1], 3.0f, t);
        t = t + v[i];
        h[i] = t * 0.0625f;
    }
}

// y = hD + 3*hC + 3*hB + hA  (hD newest = h(p+1), hA oldest = h(p-2))
__device__ __forceinline__ void emit_row(const float* __restrict__ hA,
                                         const float* __restrict__ hB,
                                         const float* __restrict__ hC,
                                         const float* __restrict__ hD,
                                         float* __restrict__ outp) {
    float y[8];
    #pragma unroll
    for (int i = 0; i < 8; i++) {
        float u = fmaf(hC[i], 3.0f, hD[i]);
        u = fmaf(hB[i], 3.0f, u);
        y[i] = u + hA[i];
    }
    *reinterpret_cast<float4*>(outp)     = make_float4(y[0], y[1], y[2], y[3]);
    *reinterpret_cast<float4*>(outp + 4) = make_float4(y[4], y[5], y[6], y[7]);
}

__global__ __launch_bounds__(256, 3)
void Blur_455266533538_kernel(const float* __restrict__ x,
                              const float* __restrict__ kern,
                              float* __restrict__ out, int nimg) {
    int tile = blockIdx.x & 3;            // 4 tiles of 64 rows per image
    int img  = blockIdx.x >> 2;
    if (img >= nimg) return;

    int tid   = threadIdx.x;
    int lane  = tid & 31;
    int chunk = tid >> 5;
    int q0 = lane * 8;
    int r0 = tile * TILE_ROWS + chunk * ROWS_PER_THREAD;

    const float* xin = x   + (size_t)img * (HH * WW);
    float*       yo  = out + (size_t)img * (HH * WW);

    // Verify kernel == outer([1,3,3,1])/16 (exact in fp32).
    bool fast = true;
    float wva[4] = {1.0f, 3.0f, 3.0f, 1.0f};
    #pragma unroll
    for (int a = 0; a < 4; a++) {
        #pragma unroll
        for (int b = 0; b < 4; b++) {
            float expect = wva[a] * wva[b] * 0.0625f;
            if (fabsf(__ldg(&kern[a * 4 + b]) - expect) > 1e-7f) fast = false;
        }
    }

    if (fast) {
        float h0[8], h1[8], h2[8], h3[8];
        float4 a0, b0, a1, b1, a2, b2, a3, b3;

        // Prologue: batch-load 3 window rows, then filter them.
        ldrow(xin, r0 - 2, q0, a0, b0);
        ldrow(xin, r0 - 1, q0, a1, b1);
        ldrow(xin, r0,     q0, a2, b2);
        hmath(a0, b0, lane, h0);
        hmath(a1, b1, lane, h1);
        hmath(a2, b2, lane, h2);

        #pragma unroll 1
        for (int pp = 0; pp < ROWS_PER_THREAD; pp += 4) {
            int p = r0 + pp;
            // Front-batch ALL loads for this block (8 x LDG.128).
            ldrow(xin, p + 1, q0, a0, b0);
            ldrow(xin, p + 2, q0, a1, b1);
            ldrow(xin, p + 3, q0, a2, b2);
            ldrow(xin, p + 4, q0, a3, b3);
            // Consume in arrival order.
            hmath(a0, b0, lane, h3);
            emit_row(h0, h1, h2, h3, yo + (p + 0) * WW + q0);
            hmath(a1, b1, lane, h0);
            emit_row(h1, h2, h3, h0, yo + (p + 1) * WW + q0);
            hmath(a2, b2, lane, h1);
            emit_row(h2, h3, h0, h1, yo + (p + 2) * WW + q0);
            hmath(a3, b3, lane, h2);
            emit_row(h3, h0, h1, h2, yo + (p + 3) * WW + q0);
        }
    } else {
        // Exact general fallback: direct 16-tap convolution.
        float kk[16];
        #pragma unroll
        for (int i = 0; i < 16; i++) kk[i] = __ldg(&kern[i]);

        for (int pr = 0; pr < ROWS_PER_THREAD; pr++) {
            int p = r0 + pr;
            for (int qc = 0; qc < 8; qc++) {
                int q = q0 + qc;
                float acc = 0.0f;
                #pragma unroll
                for (int a = 0; a < 4; a++) {
                    int rr = p + 1 - a;
                    if (rr < 0 || rr >= HH) continue;
                    #pragma unroll
                    for (int b = 0; b < 4; b++) {
                        int cc = q + 1 - b;
                        if (cc < 0 || cc >= WW) continue;
                        acc = fmaf(kk[a * 4 + b], xin[rr * WW + cc], acc);
                    }
                }
                yo[p * WW + q] = acc;
            }
        }
    }
}

extern "C" void kernel_launch(void* const* d_in, const int* in_sizes, int n_in,
                              void* d_out, int out_size) {
    const float* x    = (const float*)d_in[0];
    const float* kern = (const float*)d_in[1];
    float* out = (float*)d_out;

    int n = in_sizes[0];
    int nimg = n / (HH * WW);   // B*C images of 256x256

    Blur_455266533538_kernel<<<nimg * 4, 256>>>(x, kern, out, nimg);
}

// round 5
// speedup vs baseline: 1.2526x; 1.0248x over previous
#include <cuda_runtime.h>
#include <cuda_bf16.h>

// Blur (upfirdn2d, 4x4 FIR = outer([1,3,3,1])/16, pad=(2,1), stride 1)
// x: (B,C,256,256) fp32 -> y: same shape.
// y[p][q] = sum_{a,b} K[a][b] * x[p+1-a][q+1-b]  (zero padded)
//
// R5: fully-scripted software pipeline per 8-row strip. Prologue issues
// 14 LDG.128 back-to-back; block1 loads are issued one-per-row *during*
// block0's consume phase so the warp never drains its outstanding loads.
// Separable immediate-FMA FIR, shuffle-based horizontal halo.

#define HH 256
#define WW 256
#define TILE_ROWS 64
#define ROWS_PER_THREAD 8

// Load one row segment (two aligned float4), zero-filled out of range.
// r must be warp-uniform.
__device__ __forceinline__ void ldrow(const float* __restrict__ xin,
                                      int r, int q0, float4& a, float4& b) {
    if (r >= 0 && r < HH) {
        const float4* p = reinterpret_cast<const float4*>(xin + r * WW + q0);
        a = p[0];
        b = p[1];
    } else {
        a = make_float4(0.f, 0.f, 0.f, 0.f);
        b = a;
    }
}

// Horizontal FIR on a staged row: h[i] = (x[q+1]+3x[q]+3x[q-1]+x[q-2])/16.
// Halo via warp shuffle (warp spans the full 256-col row; lane 0/31 edges
// are exactly the conv zero-padding). Warp-collective.
__device__ __forceinline__ void hmath(float4 a, float4 b, int lane,
                                      float* __restrict__ h) {
    float lm2 = __shfl_up_sync(0xFFFFFFFFu, b.z, 1);
    float lm1 = __shfl_up_sync(0xFFFFFFFFu, b.w, 1);
    float rp1 = __shfl_down_sync(0xFFFFFFFFu, a.x, 1);
    if (lane == 0)  { lm2 = 0.0f; lm1 = 0.0f; }
    if (lane == 31) { rp1 = 0.0f; }

    float v[11];
    v[0] = lm2; v[1] = lm1;
    v[2] = a.x; v[3] = a.y; v[4] = a.z; v[5] = a.w;
    v[6] = b.x; v[7] = b.y; v[8] = b.z; v[9] = b.w;
    v[10] = rp1;

    #pragma unroll
    for (int i = 0; i < 8; i++) {
        float t = fmaf(v[i + 2], 3.0f, v[i + 3]);
        t = fmaf(v[i + 1], 3.0f, t);
        t = t + v[i];
        h[i] = t * 0.0625f;
    }
}

// y = hD + 3*hC + 3*hB + hA  (hD newest = h(p+1), hA oldest = h(p-2))
__device__ __forceinline__ void emit_row(const float* __restrict__ hA,
                                         const float* __restrict__ hB,
                                         const float* __restrict__ hC,
                                         const float* __restrict__ hD,
                                         float* __restrict__ outp) {
    float y[8];
    #pragma unroll
    for (int i = 0; i < 8; i++) {
        float u = fmaf(hC[i], 3.0f, hD[i]);
        u = fmaf(hB[i], 3.0f, u);
        y[i] = u + hA[i];
    }
    *reinterpret_cast<float4*>(outp)     = make_float4(y[0], y[1], y[2], y[3]);
    *reinterpret_cast<float4*>(outp + 4) = make_float4(y[4], y[5], y[6], y[7]);
}

__global__ __launch_bounds__(256, 2)
void Blur_455266533538_kernel(const float* __restrict__ x,
                              const float* __restrict__ kern,
                              float* __restrict__ out, int nimg) {
    int tile = blockIdx.x & 3;            // 4 tiles of 64 rows per image
    int img  = blockIdx.x >> 2;
    if (img >= nimg) return;

    int tid   = threadIdx.x;
    int lane  = tid & 31;
    int chunk = tid >> 5;
    int q0 = lane * 8;
    int r0 = tile * TILE_ROWS + chunk * ROWS_PER_THREAD;

    const float* xin = x   + (size_t)img * (HH * WW);
    float*       yo  = out + (size_t)img * (HH * WW);

    // Verify kernel == outer([1,3,3,1])/16 (exact in fp32).
    bool fast = true;
    float wva[4] = {1.0f, 3.0f, 3.0f, 1.0f};
    #pragma unroll
    for (int a = 0; a < 4; a++) {
        #pragma unroll
        for (int b = 0; b < 4; b++) {
            float expect = wva[a] * wva[b] * 0.0625f;
            if (fabsf(__ldg(&kern[a * 4 + b]) - expect) > 1e-7f) fast = false;
        }
    }

    if (fast) {
        float h0[8], h1[8], h2[8], h3[8];

        // ---- prologue: 14 LDG.128 back-to-back ----
        float4 pa0, pb0, pa1, pb1, pa2, pb2;         // halo rows r0-2..r0
        ldrow(xin, r0 - 2, q0, pa0, pb0);
        ldrow(xin, r0 - 1, q0, pa1, pb1);
        ldrow(xin, r0,     q0, pa2, pb2);
        float4 a0, b0, a1, b1, a2, b2, a3, b3;       // block0 rows r0+1..r0+4
        ldrow(xin, r0 + 1, q0, a0, b0);
        ldrow(xin, r0 + 2, q0, a1, b1);
        ldrow(xin, r0 + 3, q0, a2, b2);
        ldrow(xin, r0 + 4, q0, a3, b3);

        hmath(pa0, pb0, lane, h0);
        hmath(pa1, pb1, lane, h1);
        hmath(pa2, pb2, lane, h2);

        // ---- consume block0; issue block1 loads as staging frees ----
        float4 c0, d0, c1, d1, c2, d2, c3, d3;       // block1 rows r0+5..r0+8
        hmath(a0, b0, lane, h3);
        ldrow(xin, r0 + 5, q0, c0, d0);
        emit_row(h0, h1, h2, h3, yo + (r0 + 0) * WW + q0);

        hmath(a1, b1, lane, h0);
        ldrow(xin, r0 + 6, q0, c1, d1);
        emit_row(h1, h2, h3, h0, yo + (r0 + 1) * WW + q0);

        hmath(a2, b2, lane, h1);
        ldrow(xin, r0 + 7, q0, c2, d2);
        emit_row(h2, h3, h0, h1, yo + (r0 + 2) * WW + q0);

        hmath(a3, b3, lane, h2);
        ldrow(xin, r0 + 8, q0, c3, d3);
        emit_row(h3, h0, h1, h2, yo + (r0 + 3) * WW + q0);

        // ---- consume block1 (tail) ----
        hmath(c0, d0, lane, h3);
        emit_row(h0, h1, h2, h3, yo + (r0 + 4) * WW + q0);
        hmath(c1, d1, lane, h0);
        emit_row(h1, h2, h3, h0, yo + (r0 + 5) * WW + q0);
        hmath(c2, d2, lane, h1);
        emit_row(h2, h3, h0, h1, yo + (r0 + 6) * WW + q0);
        hmath(c3, d3, lane, h2);
        emit_row(h3, h0, h1, h2, yo + (r0 + 7) * WW + q0);
    } else {
        // Exact general fallback: direct 16-tap convolution.
        float kk[16];
        #pragma unroll
        for (int i = 0; i < 16; i++) kk[i] = __ldg(&kern[i]);

        for (int pr = 0; pr < ROWS_PER_THREAD; pr++) {
            int p = r0 + pr;
            for (int qc = 0; qc < 8; qc++) {
                int q = q0 + qc;
                float acc = 0.0f;
                #pragma unroll
                for (int a = 0; a < 4; a++) {
                    int rr = p + 1 - a;
                    if (rr < 0 || rr >= HH) continue;
                    #pragma unroll
                    for (int b = 0; b < 4; b++) {
                        int cc = q + 1 - b;
                        if (cc < 0 || cc >= WW) continue;
                        acc = fmaf(kk[a * 4 + b], xin[rr * WW + cc], acc);
                    }
                }
                yo[p * WW + q] = acc;
            }
        }
    }
}

extern "C" void kernel_launch(void* const* d_in, const int* in_sizes, int n_in,
                              void* d_out, int out_size) {
    const float* x    = (const float*)d_in[0];
    const float* kern = (const float*)d_in[1];
    float* out = (float*)d_out;

    int n = in_sizes[0];
    int nimg = n / (HH * WW);   // B*C images of 256x256

    Blur_455266533538_kernel<<<nimg * 4, 256>>>(x, kern, out, nimg);
}